// round 1
// baseline (speedup 1.0000x reference)
#include <cuda_runtime.h>
#include <math.h>

// Problem constants (fixed by the reference)
#define BB    2
#define NN    2048
#define CC    1024
#define HH    16
#define DD    64
#define E3    3072
#define MM    (BB*NN)   // 4096
#define BH    (BB*HH)   // 32

// Scratch (no allocations allowed): Q/K/V in [BH, N, D] layout, attn out in [B, N, C]
__device__ float g_q [BH * NN * DD];
__device__ float g_k [BH * NN * DD];
__device__ float g_v [BH * NN * DD];
__device__ float g_ao[MM * CC];

// ---------------------------------------------------------------------------
// GEMM 1: qkv = x[M,K] @ W_qkv[3072,K]^T, scattered into g_q/g_k/g_v
// Tile 64x64, BK=16, 256 threads, 4x4 per thread.
// ---------------------------------------------------------------------------
__global__ __launch_bounds__(256) void qkv_gemm_kernel(
    const float* __restrict__ A, const float* __restrict__ W)
{
    const int K = CC;
    __shared__ float As[16][68];   // K-major, stride 68 (float4-aligned, conflict-light)
    __shared__ float Bs[16][68];

    const int t  = threadIdx.x;
    const int tx = t & 15;
    const int ty = t >> 4;
    const int m0 = blockIdx.y * 64;
    const int n0 = blockIdx.x * 64;

    const int lr = t >> 2;          // 0..63: row within tile
    const int lk = (t & 3) * 4;     // 0,4,8,12: k offset

    float acc[4][4];
#pragma unroll
    for (int i = 0; i < 4; i++)
#pragma unroll
        for (int j = 0; j < 4; j++) acc[i][j] = 0.0f;

    for (int k0 = 0; k0 < K; k0 += 16) {
        float4 av = *(const float4*)&A[(size_t)(m0 + lr) * K + k0 + lk];
        float4 wv = *(const float4*)&W[(size_t)(n0 + lr) * K + k0 + lk];
        As[lk + 0][lr] = av.x; As[lk + 1][lr] = av.y;
        As[lk + 2][lr] = av.z; As[lk + 3][lr] = av.w;
        Bs[lk + 0][lr] = wv.x; Bs[lk + 1][lr] = wv.y;
        Bs[lk + 2][lr] = wv.z; Bs[lk + 3][lr] = wv.w;
        __syncthreads();

#pragma unroll
        for (int kk = 0; kk < 16; kk++) {
            float4 a = *(const float4*)&As[kk][ty * 4];
            float4 b = *(const float4*)&Bs[kk][tx * 4];
            float ar[4] = {a.x, a.y, a.z, a.w};
            float br[4] = {b.x, b.y, b.z, b.w};
#pragma unroll
            for (int i = 0; i < 4; i++)
#pragma unroll
                for (int j = 0; j < 4; j++)
                    acc[i][j] = fmaf(ar[i], br[j], acc[i][j]);
        }
        __syncthreads();
    }

    // Epilogue: scatter into Q/K/V [BH, N, D]
#pragma unroll
    for (int i = 0; i < 4; i++) {
        const int m = m0 + ty * 4 + i;
        const int b = m >> 11;          // /2048
        const int n = m & 2047;
#pragma unroll
        for (int j = 0; j < 4; j++) {
            const int e    = n0 + tx * 4 + j;
            const int part = e >> 10;       // 0:q 1:k 2:v
            const int r    = e & 1023;
            const int h    = r >> 6;
            const int d    = r & 63;
            float* dst = (part == 0) ? g_q : (part == 1) ? g_k : g_v;
            dst[((size_t)(b * HH + h) * NN + n) * DD + d] = acc[i][j];
        }
    }
}

// ---------------------------------------------------------------------------
// Flash attention: one block = 128 query rows of one (b,h); each thread owns
// one query row (q[64] + acc[64] in registers), streams K/V tiles of 64 rows
// through shared memory. All inner-loop shared reads are warp-broadcast.
// ---------------------------------------------------------------------------
__global__ __launch_bounds__(128) void attn_kernel()
{
    const int bh  = blockIdx.y;                 // 0..31
    const int q0  = blockIdx.x * 128;
    const int tid = threadIdx.x;

    const float* Qp = g_q + (size_t)bh * NN * DD;
    const float* Kp = g_k + (size_t)bh * NN * DD;
    const float* Vp = g_v + (size_t)bh * NN * DD;

    __shared__ float ks[64][64];
    __shared__ float vs[64][64];

    float q[DD];
#pragma unroll
    for (int d4 = 0; d4 < 16; d4++) {
        float4 v = *(const float4*)&Qp[(size_t)(q0 + tid) * DD + d4 * 4];
        q[d4 * 4 + 0] = v.x; q[d4 * 4 + 1] = v.y;
        q[d4 * 4 + 2] = v.z; q[d4 * 4 + 3] = v.w;
    }

    float acc[DD];
#pragma unroll
    for (int d = 0; d < DD; d++) acc[d] = 0.0f;
    float mi = -1e30f;
    float l  = 0.0f;

    for (int j0 = 0; j0 < NN; j0 += 64) {
        // Cooperative tile load: 64x64 K and V, float4-vectorized, coalesced
#pragma unroll
        for (int i = 0; i < 8; i++) {
            int idx = tid + i * 128;          // 0..1023 float4 slots
            int row = idx >> 4;
            int c4  = (idx & 15) * 4;
            *(float4*)&ks[row][c4] = *(const float4*)&Kp[(size_t)(j0 + row) * DD + c4];
            *(float4*)&vs[row][c4] = *(const float4*)&Vp[(size_t)(j0 + row) * DD + c4];
        }
        __syncthreads();

        for (int jj = 0; jj < 64; jj++) {
            // dot(q, k_jj) with 4 partial accumulators for ILP
            float s0 = 0.f, s1 = 0.f, s2 = 0.f, s3 = 0.f;
#pragma unroll
            for (int d4 = 0; d4 < 16; d4++) {
                float4 kv = *(const float4*)&ks[jj][d4 * 4];   // broadcast
                s0 = fmaf(q[d4 * 4 + 0], kv.x, s0);
                s1 = fmaf(q[d4 * 4 + 1], kv.y, s1);
                s2 = fmaf(q[d4 * 4 + 2], kv.z, s2);
                s3 = fmaf(q[d4 * 4 + 3], kv.w, s3);
            }
            float s = ((s0 + s1) + (s2 + s3)) * 0.125f;   // 1/sqrt(64)

            if (s > mi) {                 // rare rescale (~11x per row)
                float corr = __expf(mi - s);
                mi = s;
                l *= corr;
#pragma unroll
                for (int d = 0; d < DD; d++) acc[d] *= corr;
            }
            float p = __expf(s - mi);
            l += p;
#pragma unroll
            for (int d4 = 0; d4 < 16; d4++) {
                float4 vv = *(const float4*)&vs[jj][d4 * 4];   // broadcast
                acc[d4 * 4 + 0] = fmaf(p, vv.x, acc[d4 * 4 + 0]);
                acc[d4 * 4 + 1] = fmaf(p, vv.y, acc[d4 * 4 + 1]);
                acc[d4 * 4 + 2] = fmaf(p, vv.z, acc[d4 * 4 + 2]);
                acc[d4 * 4 + 3] = fmaf(p, vv.w, acc[d4 * 4 + 3]);
            }
        }
        __syncthreads();
    }

    const float inv = 1.0f / l;
    const int b = bh >> 4;
    const int h = bh & 15;
    const int n = q0 + tid;
    float* dst = g_ao + ((size_t)(b * NN + n)) * CC + h * DD;
#pragma unroll
    for (int d4 = 0; d4 < 16; d4++) {
        float4 o;
        o.x = acc[d4 * 4 + 0] * inv;
        o.y = acc[d4 * 4 + 1] * inv;
        o.z = acc[d4 * 4 + 2] * inv;
        o.w = acc[d4 * 4 + 3] * inv;
        *(float4*)&dst[d4 * 4] = o;
    }
}

// ---------------------------------------------------------------------------
// GEMM 2: y = attn_out[M,1024] @ W_out[1024,1024]^T + b_out
// ---------------------------------------------------------------------------
__global__ __launch_bounds__(256) void proj_gemm_kernel(
    const float* __restrict__ W, const float* __restrict__ bias,
    float* __restrict__ out)
{
    const int K = CC;
    __shared__ float As[16][68];
    __shared__ float Bs[16][68];

    const int t  = threadIdx.x;
    const int tx = t & 15;
    const int ty = t >> 4;
    const int m0 = blockIdx.y * 64;
    const int n0 = blockIdx.x * 64;

    const int lr = t >> 2;
    const int lk = (t & 3) * 4;

    float acc[4][4];
#pragma unroll
    for (int i = 0; i < 4; i++)
#pragma unroll
        for (int j = 0; j < 4; j++) acc[i][j] = 0.0f;

    const float* A = g_ao;
    for (int k0 = 0; k0 < K; k0 += 16) {
        float4 av = *(const float4*)&A[(size_t)(m0 + lr) * K + k0 + lk];
        float4 wv = *(const float4*)&W[(size_t)(n0 + lr) * K + k0 + lk];
        As[lk + 0][lr] = av.x; As[lk + 1][lr] = av.y;
        As[lk + 2][lr] = av.z; As[lk + 3][lr] = av.w;
        Bs[lk + 0][lr] = wv.x; Bs[lk + 1][lr] = wv.y;
        Bs[lk + 2][lr] = wv.z; Bs[lk + 3][lr] = wv.w;
        __syncthreads();

#pragma unroll
        for (int kk = 0; kk < 16; kk++) {
            float4 a = *(const float4*)&As[kk][ty * 4];
            float4 b = *(const float4*)&Bs[kk][tx * 4];
            float ar[4] = {a.x, a.y, a.z, a.w};
            float br[4] = {b.x, b.y, b.z, b.w};
#pragma unroll
            for (int i = 0; i < 4; i++)
#pragma unroll
                for (int j = 0; j < 4; j++)
                    acc[i][j] = fmaf(ar[i], br[j], acc[i][j]);
        }
        __syncthreads();
    }

#pragma unroll
    for (int i = 0; i < 4; i++) {
        const int m = m0 + ty * 4 + i;
#pragma unroll
        for (int j = 0; j < 4; j++) {
            const int n = n0 + tx * 4 + j;
            out[(size_t)m * CC + n] = acc[i][j] + bias[n];
        }
    }
}

// ---------------------------------------------------------------------------
extern "C" void kernel_launch(void* const* d_in, const int* in_sizes, int n_in,
                              void* d_out, int out_size)
{
    const float* x     = (const float*)d_in[0];   // [2,2048,1024]
    const float* W_qkv = (const float*)d_in[1];   // [3072,1024]
    const float* W_out = (const float*)d_in[2];   // [1024,1024]
    const float* b_out = (const float*)d_in[3];   // [1024]
    float* out = (float*)d_out;                   // [2,2048,1024]

    (void)in_sizes; (void)n_in; (void)out_size;

    // 1) QKV projection + scatter to [BH,N,D]
    {
        dim3 grid(E3 / 64, MM / 64);   // (48, 64)
        qkv_gemm_kernel<<<grid, 256>>>(x, W_qkv);
    }
    // 2) Flash attention
    {
        dim3 grid(NN / 128, BH);       // (16, 32)
        attn_kernel<<<grid, 128>>>();
    }
    // 3) Output projection + bias
    {
        dim3 grid(CC / 64, MM / 64);   // (16, 64)
        proj_gemm_kernel<<<grid, 256>>>(W_out, b_out, out);
    }
}

// round 2
// speedup vs baseline: 1.1299x; 1.1299x over previous
#include <cuda_runtime.h>
#include <math.h>

// Problem constants (fixed by the reference)
#define BB    2
#define NN    2048
#define CC    1024
#define HH    16
#define DD    64
#define E3    3072
#define MM    (BB*NN)   // 4096
#define BH    (BB*HH)   // 32

// Scratch (no allocations allowed)
__device__ float g_q [BH * NN * DD];
__device__ float g_k [BH * NN * DD];
__device__ float g_v [BH * NN * DD];
__device__ float g_ao[MM * CC];

// ---------------------------------------------------------------------------
// GEMM 1: qkv = x[M,1024] @ W_qkv[3072,1024]^T, scattered into g_q/g_k/g_v
// 128x128 tile, BK=8, 256 threads, 8x8 per thread (4+4 split).
// ---------------------------------------------------------------------------
__global__ __launch_bounds__(256) void qkv_gemm_kernel(
    const float* __restrict__ A, const float* __restrict__ W)
{
    __shared__ float As[8][132];   // stride 132: conflict-free STS
    __shared__ float Bs[8][132];

    const int t  = threadIdx.x;
    const int tx = t & 15;
    const int ty = t >> 4;
    const int m0 = blockIdx.y * 128;
    const int n0 = blockIdx.x * 128;

    const int lr = t >> 1;          // 0..127
    const int lk = (t & 1) * 4;     // 0 or 4

    const float* Aptr = A + (size_t)(m0 + lr) * CC + lk;
    const float* Wptr = W + (size_t)(n0 + lr) * CC + lk;

    float4 a_pre = *(const float4*)Aptr;
    float4 b_pre = *(const float4*)Wptr;

    float acc[8][8];
#pragma unroll
    for (int i = 0; i < 8; i++)
#pragma unroll
        for (int j = 0; j < 8; j++) acc[i][j] = 0.0f;

    for (int k0 = 0; k0 < CC; k0 += 8) {
        As[lk + 0][lr] = a_pre.x; As[lk + 1][lr] = a_pre.y;
        As[lk + 2][lr] = a_pre.z; As[lk + 3][lr] = a_pre.w;
        Bs[lk + 0][lr] = b_pre.x; Bs[lk + 1][lr] = b_pre.y;
        Bs[lk + 2][lr] = b_pre.z; Bs[lk + 3][lr] = b_pre.w;
        __syncthreads();

        if (k0 + 8 < CC) {
            a_pre = *(const float4*)(Aptr + k0 + 8);
            b_pre = *(const float4*)(Wptr + k0 + 8);
        }

#pragma unroll
        for (int kk = 0; kk < 8; kk++) {
            float4 a0 = *(const float4*)&As[kk][ty * 4];
            float4 a1 = *(const float4*)&As[kk][ty * 4 + 64];
            float4 b0 = *(const float4*)&Bs[kk][tx * 4];
            float4 b1 = *(const float4*)&Bs[kk][tx * 4 + 64];
            float ar[8] = {a0.x, a0.y, a0.z, a0.w, a1.x, a1.y, a1.z, a1.w};
            float br[8] = {b0.x, b0.y, b0.z, b0.w, b1.x, b1.y, b1.z, b1.w};
#pragma unroll
            for (int i = 0; i < 8; i++)
#pragma unroll
                for (int j = 0; j < 8; j++)
                    acc[i][j] = fmaf(ar[i], br[j], acc[i][j]);
        }
        __syncthreads();
    }

    // Epilogue: scatter into Q/K/V [BH, N, D]
#pragma unroll
    for (int i = 0; i < 8; i++) {
        const int m = m0 + ((i < 4) ? (ty * 4 + i) : (64 + ty * 4 + i - 4));
        const int b = m >> 11;
        const int n = m & 2047;
#pragma unroll
        for (int j = 0; j < 8; j++) {
            const int e    = n0 + ((j < 4) ? (tx * 4 + j) : (64 + tx * 4 + j - 4));
            const int part = e >> 10;
            const int r    = e & 1023;
            const int h    = r >> 6;
            const int d    = r & 63;
            float* dst = (part == 0) ? g_q : (part == 1) ? g_k : g_v;
            dst[((size_t)(b * HH + h) * NN + n) * DD + d] = acc[i][j];
        }
    }
}

// ---------------------------------------------------------------------------
// Flash attention, D-split: 256 threads = 128 queries x 2 halves.
// Lane pair (lane, lane^16) shares a query; each owns 32 of 64 dims.
// Full score via one shfl_xor. Streams 64-key K/V tiles through smem.
// ---------------------------------------------------------------------------
__global__ __launch_bounds__(256) void attn_kernel()
{
    const int bh   = blockIdx.y;
    const int q0   = blockIdx.x * 128;
    const int tid  = threadIdx.x;
    const int lane = tid & 31;
    const int warp = tid >> 5;
    const int qrow = warp * 16 + (lane & 15);     // 0..127
    const int half = lane >> 4;                   // 0 or 1
    const int hoff = half * 32;

    const float* Qp = g_q + (size_t)bh * NN * DD;
    const float* Kp = g_k + (size_t)bh * NN * DD;
    const float* Vp = g_v + (size_t)bh * NN * DD;

    __shared__ float ks[64][64];
    __shared__ float vs[64][64];

    float q[32];
#pragma unroll
    for (int d4 = 0; d4 < 8; d4++) {
        float4 v = *(const float4*)&Qp[(size_t)(q0 + qrow) * DD + hoff + d4 * 4];
        q[d4 * 4 + 0] = v.x; q[d4 * 4 + 1] = v.y;
        q[d4 * 4 + 2] = v.z; q[d4 * 4 + 3] = v.w;
    }

    float acc[32];
#pragma unroll
    for (int d = 0; d < 32; d++) acc[d] = 0.0f;
    float mi = -1e30f;
    float l  = 0.0f;

    for (int j0 = 0; j0 < NN; j0 += 64) {
        // Cooperative tile load: 64x64 K and V (1024 float4 each)
#pragma unroll
        for (int i = 0; i < 4; i++) {
            int idx = tid + i * 256;
            int row = idx >> 4;
            int c4  = (idx & 15) * 4;
            *(float4*)&ks[row][c4] = *(const float4*)&Kp[(size_t)(j0 + row) * DD + c4];
            *(float4*)&vs[row][c4] = *(const float4*)&Vp[(size_t)(j0 + row) * DD + c4];
        }
        __syncthreads();

        for (int jj = 0; jj < 64; jj++) {
            // half-dot with 4 partial accumulators
            float s0 = 0.f, s1 = 0.f, s2 = 0.f, s3 = 0.f;
#pragma unroll
            for (int d4 = 0; d4 < 8; d4++) {
                float4 kv = *(const float4*)&ks[jj][hoff + d4 * 4];
                s0 = fmaf(q[d4 * 4 + 0], kv.x, s0);
                s1 = fmaf(q[d4 * 4 + 1], kv.y, s1);
                s2 = fmaf(q[d4 * 4 + 2], kv.z, s2);
                s3 = fmaf(q[d4 * 4 + 3], kv.w, s3);
            }
            float sp = (s0 + s1) + (s2 + s3);
            float s  = (sp + __shfl_xor_sync(0xffffffffu, sp, 16)) * 0.125f;

            if (s > mi) {                 // rare rescale
                float corr = __expf(mi - s);
                mi = s;
                l *= corr;
#pragma unroll
                for (int d = 0; d < 32; d++) acc[d] *= corr;
            }
            float p = __expf(s - mi);
            l += p;
#pragma unroll
            for (int d4 = 0; d4 < 8; d4++) {
                float4 vv = *(const float4*)&vs[jj][hoff + d4 * 4];
                acc[d4 * 4 + 0] = fmaf(p, vv.x, acc[d4 * 4 + 0]);
                acc[d4 * 4 + 1] = fmaf(p, vv.y, acc[d4 * 4 + 1]);
                acc[d4 * 4 + 2] = fmaf(p, vv.z, acc[d4 * 4 + 2]);
                acc[d4 * 4 + 3] = fmaf(p, vv.w, acc[d4 * 4 + 3]);
            }
        }
        __syncthreads();
    }

    const float inv = 1.0f / l;
    const int b = bh >> 4;
    const int h = bh & 15;
    const int n = q0 + qrow;
    float* dst = g_ao + ((size_t)(b * NN + n)) * CC + h * DD + hoff;
#pragma unroll
    for (int d4 = 0; d4 < 8; d4++) {
        float4 o;
        o.x = acc[d4 * 4 + 0] * inv;
        o.y = acc[d4 * 4 + 1] * inv;
        o.z = acc[d4 * 4 + 2] * inv;
        o.w = acc[d4 * 4 + 3] * inv;
        *(float4*)&dst[d4 * 4] = o;
    }
}

// ---------------------------------------------------------------------------
// GEMM 2: y = attn_out[M,1024] @ W_out[1024,1024]^T + b_out
// Same 128x128x8 structure.
// ---------------------------------------------------------------------------
__global__ __launch_bounds__(256) void proj_gemm_kernel(
    const float* __restrict__ W, const float* __restrict__ bias,
    float* __restrict__ out)
{
    __shared__ float As[8][132];
    __shared__ float Bs[8][132];

    const int t  = threadIdx.x;
    const int tx = t & 15;
    const int ty = t >> 4;
    const int m0 = blockIdx.y * 128;
    const int n0 = blockIdx.x * 128;

    const int lr = t >> 1;
    const int lk = (t & 1) * 4;

    const float* Aptr = g_ao + (size_t)(m0 + lr) * CC + lk;
    const float* Wptr = W    + (size_t)(n0 + lr) * CC + lk;

    float4 a_pre = *(const float4*)Aptr;
    float4 b_pre = *(const float4*)Wptr;

    float acc[8][8];
#pragma unroll
    for (int i = 0; i < 8; i++)
#pragma unroll
        for (int j = 0; j < 8; j++) acc[i][j] = 0.0f;

    for (int k0 = 0; k0 < CC; k0 += 8) {
        As[lk + 0][lr] = a_pre.x; As[lk + 1][lr] = a_pre.y;
        As[lk + 2][lr] = a_pre.z; As[lk + 3][lr] = a_pre.w;
        Bs[lk + 0][lr] = b_pre.x; Bs[lk + 1][lr] = b_pre.y;
        Bs[lk + 2][lr] = b_pre.z; Bs[lk + 3][lr] = b_pre.w;
        __syncthreads();

        if (k0 + 8 < CC) {
            a_pre = *(const float4*)(Aptr + k0 + 8);
            b_pre = *(const float4*)(Wptr + k0 + 8);
        }

#pragma unroll
        for (int kk = 0; kk < 8; kk++) {
            float4 a0 = *(const float4*)&As[kk][ty * 4];
            float4 a1 = *(const float4*)&As[kk][ty * 4 + 64];
            float4 b0 = *(const float4*)&Bs[kk][tx * 4];
            float4 b1 = *(const float4*)&Bs[kk][tx * 4 + 64];
            float ar[8] = {a0.x, a0.y, a0.z, a0.w, a1.x, a1.y, a1.z, a1.w};
            float br[8] = {b0.x, b0.y, b0.z, b0.w, b1.x, b1.y, b1.z, b1.w};
#pragma unroll
            for (int i = 0; i < 8; i++)
#pragma unroll
                for (int j = 0; j < 8; j++)
                    acc[i][j] = fmaf(ar[i], br[j], acc[i][j]);
        }
        __syncthreads();
    }

#pragma unroll
    for (int i = 0; i < 8; i++) {
        const int m = m0 + ((i < 4) ? (ty * 4 + i) : (64 + ty * 4 + i - 4));
#pragma unroll
        for (int j = 0; j < 8; j++) {
            const int n = n0 + ((j < 4) ? (tx * 4 + j) : (64 + tx * 4 + j - 4));
            out[(size_t)m * CC + n] = acc[i][j] + bias[n];
        }
    }
}

// ---------------------------------------------------------------------------
extern "C" void kernel_launch(void* const* d_in, const int* in_sizes, int n_in,
                              void* d_out, int out_size)
{
    const float* x     = (const float*)d_in[0];   // [2,2048,1024]
    const float* W_qkv = (const float*)d_in[1];   // [3072,1024]
    const float* W_out = (const float*)d_in[2];   // [1024,1024]
    const float* b_out = (const float*)d_in[3];   // [1024]
    float* out = (float*)d_out;                   // [2,2048,1024]

    (void)in_sizes; (void)n_in; (void)out_size;

    {
        dim3 grid(E3 / 128, MM / 128);   // (24, 32)
        qkv_gemm_kernel<<<grid, 256>>>(x, W_qkv);
    }
    {
        dim3 grid(NN / 128, BH);         // (16, 32)
        attn_kernel<<<grid, 256>>>();
    }
    {
        dim3 grid(CC / 128, MM / 128);   // (8, 32)
        proj_gemm_kernel<<<grid, 256>>>(W_out, b_out, out);
    }
}

// round 5
// speedup vs baseline: 1.4126x; 1.2502x over previous
#include <cuda_runtime.h>
#include <cuda_fp16.h>
#include <cstdint>
#include <math.h>

#define BB 2
#define NN 2048
#define CC 1024
#define HH 16
#define DD 64
#define E3 3072
#define MM (BB*NN)   // 4096
#define BH (BB*HH)   // 32

// ---------------- scratch (no allocations allowed) ----------------
__device__ float  g_q [BH * NN * DD];
__device__ float  g_k [BH * NN * DD];
__device__ float  g_v [BH * NN * DD];
__device__ float  g_ao[MM * CC];
__device__ __half g_xh [MM * CC],  g_xl [MM * CC];
__device__ __half g_wqh[E3 * CC],  g_wql[E3 * CC];
__device__ __half g_woh[CC * CC],  g_wol[CC * CC];
__device__ __half g_aoh[MM * CC],  g_aol[MM * CC];

__device__ __forceinline__ uint32_t smem_u32(const void* p) {
    uint32_t a;
    asm("{ .reg .u64 t; cvta.to.shared.u64 t, %1; cvt.u32.u64 %0, t; }" : "=r"(a) : "l"(p));
    return a;
}

// ---------------- split kernel: fp32 -> (fp16 hi, fp16 lo) ----------------
// which: 0 x->g_xh/l   1 W_qkv->g_wqh/l   2 W_out->g_woh/l   3 g_ao->g_aoh/l
__global__ __launch_bounds__(256) void split_kernel(const float* __restrict__ src_in,
                                                    int which, int n4)
{
    const float* src = (which == 3) ? g_ao : src_in;
    __half* hi; __half* lo;
    if (which == 0)      { hi = g_xh;  lo = g_xl;  }
    else if (which == 1) { hi = g_wqh; lo = g_wql; }
    else if (which == 2) { hi = g_woh; lo = g_wol; }
    else                 { hi = g_aoh; lo = g_aol; }

    int i = blockIdx.x * blockDim.x + threadIdx.x;
    if (i >= n4) return;
    float4 a = ((const float4*)src)[i];
    __half h0 = __float2half_rn(a.x), h1 = __float2half_rn(a.y);
    __half h2 = __float2half_rn(a.z), h3 = __float2half_rn(a.w);
    __half l0 = __float2half_rn(a.x - __half2float(h0));
    __half l1 = __float2half_rn(a.y - __half2float(h1));
    __half l2 = __float2half_rn(a.z - __half2float(h2));
    __half l3 = __float2half_rn(a.w - __half2float(h3));
    __half2* hp = (__half2*)(hi + (size_t)i * 4);
    __half2* lp = (__half2*)(lo + (size_t)i * 4);
    hp[0] = __halves2half2(h0, h1); hp[1] = __halves2half2(h2, h3);
    lp[0] = __halves2half2(l0, l1); lp[1] = __halves2half2(l2, l3);
}

// ---------------- mma.sync fp16-split GEMM ----------------
// D[m=token][n=feature] = sum_k A[m][k]*B[n][k] with 3-product fp16 split.
// Tile 128x128, BK=32 halves, 512 threads = 16 warps (4x4), warp tile 32x32.
// MODE 0: A = x split, B = W_qkv split, scatter to g_q/g_k/g_v
// MODE 1: A = ao split, B = W_out split, out += bias
#define APAD 40
template<int MODE>
__global__ __launch_bounds__(512) void tc_gemm(const float* __restrict__ bias,
                                               float* __restrict__ outp)
{
    __shared__ __half Ah[128][APAD], Al[128][APAD];
    __shared__ __half Bh[128][APAD], Bl[128][APAD];

    const int tid  = threadIdx.x;
    const int lane = tid & 31;
    const int wid  = tid >> 5;
    const int wm   = wid >> 2;        // 0..3 : 32 rows each
    const int wn   = wid & 3;         // 0..3 : 32 cols each
    const int m0 = blockIdx.y * 128;  // token tile
    const int n0 = blockIdx.x * 128;  // feature tile

    const __half* pAh = (MODE == 0) ? g_xh  : g_aoh;
    const __half* pAl = (MODE == 0) ? g_xl  : g_aol;
    const __half* pBh = (MODE == 0) ? g_wqh : g_woh;
    const __half* pBl = (MODE == 0) ? g_wql : g_wol;

    // per-thread global slot: 512 float4 slots (128 rows x 4 groups of 8 halves)
    const int grow = tid >> 2;        // 0..127
    const int gc   = (tid & 3) * 8;   // half offset within row

    const __half* gAh = pAh + (size_t)(m0 + grow) * CC + gc;
    const __half* gAl = pAl + (size_t)(m0 + grow) * CC + gc;
    const __half* gBh = pBh + (size_t)(n0 + grow) * CC + gc;
    const __half* gBl = pBl + (size_t)(n0 + grow) * CC + gc;

    float acc[2][4][4];
#pragma unroll
    for (int i = 0; i < 2; i++)
#pragma unroll
        for (int j = 0; j < 4; j++)
#pragma unroll
            for (int c = 0; c < 4; c++) acc[i][j][c] = 0.0f;

    float4 rah = *(const float4*)gAh;
    float4 ral = *(const float4*)gAl;
    float4 rbh = *(const float4*)gBh;
    float4 rbl = *(const float4*)gBl;

    const uint32_t sAh = smem_u32(&Ah[0][0]);
    const uint32_t sAl = smem_u32(&Al[0][0]);
    const uint32_t sBh = smem_u32(&Bh[0][0]);
    const uint32_t sBl = smem_u32(&Bl[0][0]);

    // ldmatrix addressing
    const uint32_t a_row = wm * 32 + (lane & 15);
    const uint32_t a_kg  = (lane >> 4) << 3;             // 0 or 8 halves
    const uint32_t b_kg  = ((lane >> 3) & 1) << 3;       // 0 or 8 halves (lanes 0-15)

    for (int k0 = 0; k0 < CC; k0 += 32) {
        __syncthreads();
        *(float4*)&Ah[grow][gc] = rah;
        *(float4*)&Al[grow][gc] = ral;
        *(float4*)&Bh[grow][gc] = rbh;
        *(float4*)&Bl[grow][gc] = rbl;
        __syncthreads();

        if (k0 + 32 < CC) {
            rah = *(const float4*)(gAh + k0 + 32);
            ral = *(const float4*)(gAl + k0 + 32);
            rbh = *(const float4*)(gBh + k0 + 32);
            rbl = *(const float4*)(gBl + k0 + 32);
        }

#pragma unroll
        for (int ks = 0; ks < 2; ks++) {
            const uint32_t kcol = ks * 16;
            uint32_t ah[2][4], al[2][4];
#pragma unroll
            for (int mt = 0; mt < 2; mt++) {
                uint32_t off = ((a_row + mt * 16) * APAD + kcol + a_kg) * 2;
                asm volatile("ldmatrix.sync.aligned.m8n8.x4.shared.b16 {%0,%1,%2,%3}, [%4];"
                    : "=r"(ah[mt][0]), "=r"(ah[mt][1]), "=r"(ah[mt][2]), "=r"(ah[mt][3])
                    : "r"(sAh + off));
                asm volatile("ldmatrix.sync.aligned.m8n8.x4.shared.b16 {%0,%1,%2,%3}, [%4];"
                    : "=r"(al[mt][0]), "=r"(al[mt][1]), "=r"(al[mt][2]), "=r"(al[mt][3])
                    : "r"(sAl + off));
            }
#pragma unroll
            for (int nt = 0; nt < 4; nt++) {
                // B fragment: NON-trans ldmatrix on [n][k] smem layout.
                // lanes 0-7 -> rows n..n+7 @ kcol (b0: k 0-7), lanes 8-15 -> same rows @ kcol+8 (b1)
                uint32_t boff = ((wn * 32 + nt * 8 + (lane & 7)) * APAD + kcol + b_kg) * 2;
                uint32_t bhr[2], blr[2];
                asm volatile("ldmatrix.sync.aligned.m8n8.x2.shared.b16 {%0,%1}, [%2];"
                    : "=r"(bhr[0]), "=r"(bhr[1]) : "r"(sBh + boff));
                asm volatile("ldmatrix.sync.aligned.m8n8.x2.shared.b16 {%0,%1}, [%2];"
                    : "=r"(blr[0]), "=r"(blr[1]) : "r"(sBl + boff));
#pragma unroll
                for (int mt = 0; mt < 2; mt++) {
                    float* c = acc[mt][nt];
                    asm volatile("mma.sync.aligned.m16n8k16.row.col.f32.f16.f16.f32 "
                        "{%0,%1,%2,%3}, {%4,%5,%6,%7}, {%8,%9}, {%0,%1,%2,%3};"
                        : "+f"(c[0]), "+f"(c[1]), "+f"(c[2]), "+f"(c[3])
                        : "r"(ah[mt][0]), "r"(ah[mt][1]), "r"(ah[mt][2]), "r"(ah[mt][3]),
                          "r"(bhr[0]), "r"(bhr[1]));
                    asm volatile("mma.sync.aligned.m16n8k16.row.col.f32.f16.f16.f32 "
                        "{%0,%1,%2,%3}, {%4,%5,%6,%7}, {%8,%9}, {%0,%1,%2,%3};"
                        : "+f"(c[0]), "+f"(c[1]), "+f"(c[2]), "+f"(c[3])
                        : "r"(ah[mt][0]), "r"(ah[mt][1]), "r"(ah[mt][2]), "r"(ah[mt][3]),
                          "r"(blr[0]), "r"(blr[1]));
                    asm volatile("mma.sync.aligned.m16n8k16.row.col.f32.f16.f16.f32 "
                        "{%0,%1,%2,%3}, {%4,%5,%6,%7}, {%8,%9}, {%0,%1,%2,%3};"
                        : "+f"(c[0]), "+f"(c[1]), "+f"(c[2]), "+f"(c[3])
                        : "r"(al[mt][0]), "r"(al[mt][1]), "r"(al[mt][2]), "r"(al[mt][3]),
                          "r"(bhr[0]), "r"(bhr[1]));
                }
            }
        }
    }

    // Epilogue: thread element (row, col) per accumulator fragment
#pragma unroll
    for (int mt = 0; mt < 2; mt++) {
#pragma unroll
        for (int nt = 0; nt < 4; nt++) {
            const float* c = acc[mt][nt];
            const int col = n0 + wn * 32 + nt * 8 + (lane & 3) * 2;   // feature e (even)
#pragma unroll
            for (int hr = 0; hr < 2; hr++) {
                const int row = m0 + wm * 32 + mt * 16 + (lane >> 2) + hr * 8;  // token
                float2 val = make_float2(c[hr * 2 + 0], c[hr * 2 + 1]);
                if (MODE == 0) {
                    const int part = col >> 10, rr = col & 1023;
                    const int h = rr >> 6, d = rr & 63;
                    float* dst = (part == 0) ? g_q : (part == 1) ? g_k : g_v;
                    const int b = row >> 11, n = row & 2047;
                    *(float2*)&dst[((size_t)(b * HH + h) * NN + n) * DD + d] = val;
                } else {
                    val.x += bias[col];
                    val.y += bias[col + 1];
                    *(float2*)&outp[(size_t)row * CC + col] = val;
                }
            }
        }
    }
}

// ---------------- Flash attention (fp32, D-split, 2-key unroll) ----------------
__global__ __launch_bounds__(256) void attn_kernel()
{
    const int bh   = blockIdx.y;
    const int q0   = blockIdx.x * 128;
    const int tid  = threadIdx.x;
    const int lane = tid & 31;
    const int warp = tid >> 5;
    const int qrow = warp * 16 + (lane & 15);
    const int half = lane >> 4;
    const int hoff = half * 32;

    const float* Qp = g_q + (size_t)bh * NN * DD;
    const float* Kp = g_k + (size_t)bh * NN * DD;
    const float* Vp = g_v + (size_t)bh * NN * DD;

    __shared__ float ks[64][64];
    __shared__ float vs[64][64];

    float q[32];
#pragma unroll
    for (int d4 = 0; d4 < 8; d4++) {
        float4 v = *(const float4*)&Qp[(size_t)(q0 + qrow) * DD + hoff + d4 * 4];
        q[d4 * 4 + 0] = v.x; q[d4 * 4 + 1] = v.y;
        q[d4 * 4 + 2] = v.z; q[d4 * 4 + 3] = v.w;
    }

    float acc[32];
#pragma unroll
    for (int d = 0; d < 32; d++) acc[d] = 0.0f;
    float mi = -1e30f;
    float l  = 0.0f;

    for (int j0 = 0; j0 < NN; j0 += 64) {
#pragma unroll
        for (int i = 0; i < 4; i++) {
            int idx = tid + i * 256;
            int row = idx >> 4;
            int c4  = (idx & 15) * 4;
            *(float4*)&ks[row][c4] = *(const float4*)&Kp[(size_t)(j0 + row) * DD + c4];
            *(float4*)&vs[row][c4] = *(const float4*)&Vp[(size_t)(j0 + row) * DD + c4];
        }
        __syncthreads();

        for (int jj = 0; jj < 64; jj += 2) {
            float a0 = 0.f, a1 = 0.f, a2 = 0.f, a3 = 0.f;
            float b0 = 0.f, b1 = 0.f, b2 = 0.f, b3 = 0.f;
#pragma unroll
            for (int d4 = 0; d4 < 8; d4++) {
                float4 ka = *(const float4*)&ks[jj][hoff + d4 * 4];
                float4 kb = *(const float4*)&ks[jj + 1][hoff + d4 * 4];
                a0 = fmaf(q[d4 * 4 + 0], ka.x, a0);
                a1 = fmaf(q[d4 * 4 + 1], ka.y, a1);
                a2 = fmaf(q[d4 * 4 + 2], ka.z, a2);
                a3 = fmaf(q[d4 * 4 + 3], ka.w, a3);
                b0 = fmaf(q[d4 * 4 + 0], kb.x, b0);
                b1 = fmaf(q[d4 * 4 + 1], kb.y, b1);
                b2 = fmaf(q[d4 * 4 + 2], kb.z, b2);
                b3 = fmaf(q[d4 * 4 + 3], kb.w, b3);
            }
            float spa = (a0 + a1) + (a2 + a3);
            float spb = (b0 + b1) + (b2 + b3);
            float sa = (spa + __shfl_xor_sync(0xffffffffu, spa, 16)) * 0.125f;
            float sb = (spb + __shfl_xor_sync(0xffffffffu, spb, 16)) * 0.125f;

            float mnew = fmaxf(mi, fmaxf(sa, sb));
            if (mnew > mi) {
                float corr = __expf(mi - mnew);
                mi = mnew;
                l *= corr;
#pragma unroll
                for (int d = 0; d < 32; d++) acc[d] *= corr;
            }
            float pa = __expf(sa - mi);
            float pb = __expf(sb - mi);
            l += pa + pb;
#pragma unroll
            for (int d4 = 0; d4 < 8; d4++) {
                float4 va = *(const float4*)&vs[jj][hoff + d4 * 4];
                float4 vb = *(const float4*)&vs[jj + 1][hoff + d4 * 4];
                acc[d4 * 4 + 0] = fmaf(pa, va.x, fmaf(pb, vb.x, acc[d4 * 4 + 0]));
                acc[d4 * 4 + 1] = fmaf(pa, va.y, fmaf(pb, vb.y, acc[d4 * 4 + 1]));
                acc[d4 * 4 + 2] = fmaf(pa, va.z, fmaf(pb, vb.z, acc[d4 * 4 + 2]));
                acc[d4 * 4 + 3] = fmaf(pa, va.w, fmaf(pb, vb.w, acc[d4 * 4 + 3]));
            }
        }
        __syncthreads();
    }

    const float inv = 1.0f / l;
    const int b = bh >> 4;
    const int h = bh & 15;
    const int n = q0 + qrow;
    float* dst = g_ao + ((size_t)(b * NN + n)) * CC + h * DD + hoff;
#pragma unroll
    for (int d4 = 0; d4 < 8; d4++) {
        float4 o;
        o.x = acc[d4 * 4 + 0] * inv;
        o.y = acc[d4 * 4 + 1] * inv;
        o.z = acc[d4 * 4 + 2] * inv;
        o.w = acc[d4 * 4 + 3] * inv;
        *(float4*)&dst[d4 * 4] = o;
    }
}

// ---------------------------------------------------------------------------
extern "C" void kernel_launch(void* const* d_in, const int* in_sizes, int n_in,
                              void* d_out, int out_size)
{
    const float* x     = (const float*)d_in[0];   // [2,2048,1024]
    const float* W_qkv = (const float*)d_in[1];   // [3072,1024]
    const float* W_out = (const float*)d_in[2];   // [1024,1024]
    const float* b_out = (const float*)d_in[3];   // [1024]
    float* out = (float*)d_out;                   // [2,2048,1024]
    (void)in_sizes; (void)n_in; (void)out_size;

    // 1) fp16 hi/lo splits of x, W_qkv, W_out
    split_kernel<<<(MM * CC / 4 + 255) / 256, 256>>>(x,     0, MM * CC / 4);
    split_kernel<<<(E3 * CC / 4 + 255) / 256, 256>>>(W_qkv, 1, E3 * CC / 4);
    split_kernel<<<(CC * CC / 4 + 255) / 256, 256>>>(W_out, 2, CC * CC / 4);

    // 2) QKV projection on tensor cores (mma.sync), scatter to g_q/g_k/g_v
    {
        dim3 grid(E3 / 128, MM / 128);   // (24, 32)
        tc_gemm<0><<<grid, 512>>>(nullptr, nullptr);
    }
    // 3) Flash attention (fp32)
    {
        dim3 grid(NN / 128, BH);
        attn_kernel<<<grid, 256>>>();
    }
    // 4) Split attention output
    split_kernel<<<(MM * CC / 4 + 255) / 256, 256>>>(nullptr, 3, MM * CC / 4);

    // 5) Output projection + bias on tensor cores
    {
        dim3 grid(CC / 128, MM / 128);   // (8, 32)
        tc_gemm<1><<<grid, 512>>>(b_out, out);
    }
}

// round 6
// speedup vs baseline: 3.1168x; 2.2064x over previous
#include <cuda_runtime.h>
#include <cuda_fp16.h>
#include <cstdint>
#include <math.h>

#define BB 2
#define NN 2048
#define CC 1024
#define HH 16
#define DD 64
#define E3 3072
#define MM (BB*NN)   // 4096
#define BH (BB*HH)   // 32

// ---------------- scratch (no allocations allowed) ----------------
__device__ float  g_q [BH * NN * DD];
__device__ float  g_k [BH * NN * DD];
__device__ float  g_v [BH * NN * DD];
__device__ float  g_ao[MM * CC];
__device__ __half g_xh [MM * CC],  g_xl [MM * CC];
__device__ __half g_wqh[E3 * CC],  g_wql[E3 * CC];
__device__ __half g_woh[CC * CC],  g_wol[CC * CC];
__device__ __half g_aoh[MM * CC],  g_aol[MM * CC];

__device__ __forceinline__ uint32_t smem_u32(const void* p) {
    uint32_t a;
    asm("{ .reg .u64 t; cvta.to.shared.u64 t, %1; cvt.u32.u64 %0, t; }" : "=r"(a) : "l"(p));
    return a;
}
__device__ __forceinline__ void mma16816(float* c, const uint32_t* a, const uint32_t* b) {
    asm volatile("mma.sync.aligned.m16n8k16.row.col.f32.f16.f16.f32 "
        "{%0,%1,%2,%3}, {%4,%5,%6,%7}, {%8,%9}, {%0,%1,%2,%3};"
        : "+f"(c[0]), "+f"(c[1]), "+f"(c[2]), "+f"(c[3])
        : "r"(a[0]), "r"(a[1]), "r"(a[2]), "r"(a[3]), "r"(b[0]), "r"(b[1]));
}
__device__ __forceinline__ void ldsm_x4(uint32_t* r, uint32_t addr) {
    asm volatile("ldmatrix.sync.aligned.m8n8.x4.shared.b16 {%0,%1,%2,%3}, [%4];"
        : "=r"(r[0]), "=r"(r[1]), "=r"(r[2]), "=r"(r[3]) : "r"(addr));
}
__device__ __forceinline__ void ldsm_x2(uint32_t* r, uint32_t addr) {
    asm volatile("ldmatrix.sync.aligned.m8n8.x2.shared.b16 {%0,%1}, [%2];"
        : "=r"(r[0]), "=r"(r[1]) : "r"(addr));
}
__device__ __forceinline__ void ldsm_x2t(uint32_t* r, uint32_t addr) {
    asm volatile("ldmatrix.sync.aligned.m8n8.x2.trans.shared.b16 {%0,%1}, [%2];"
        : "=r"(r[0]), "=r"(r[1]) : "r"(addr));
}
__device__ __forceinline__ uint32_t packh2(__half a, __half b) {
    __half2 t = __halves2half2(a, b);
    return *reinterpret_cast<uint32_t*>(&t);
}

// ---------------- split kernel: fp32 -> (fp16 hi, fp16 lo) ----------------
__global__ __launch_bounds__(256) void split_kernel(const float* __restrict__ src_in,
                                                    int which, int n4)
{
    const float* src = (which == 3) ? g_ao : src_in;
    __half* hi; __half* lo;
    if (which == 0)      { hi = g_xh;  lo = g_xl;  }
    else if (which == 1) { hi = g_wqh; lo = g_wql; }
    else if (which == 2) { hi = g_woh; lo = g_wol; }
    else                 { hi = g_aoh; lo = g_aol; }

    int i = blockIdx.x * blockDim.x + threadIdx.x;
    if (i >= n4) return;
    float4 a = ((const float4*)src)[i];
    __half h0 = __float2half_rn(a.x), h1 = __float2half_rn(a.y);
    __half h2 = __float2half_rn(a.z), h3 = __float2half_rn(a.w);
    __half l0 = __float2half_rn(a.x - __half2float(h0));
    __half l1 = __float2half_rn(a.y - __half2float(h1));
    __half l2 = __float2half_rn(a.z - __half2float(h2));
    __half l3 = __float2half_rn(a.w - __half2float(h3));
    __half2* hp = (__half2*)(hi + (size_t)i * 4);
    __half2* lp = (__half2*)(lo + (size_t)i * 4);
    hp[0] = __halves2half2(h0, h1); hp[1] = __halves2half2(h2, h3);
    lp[0] = __halves2half2(l0, l1); lp[1] = __halves2half2(l2, l3);
}

// ---------------- mma.sync fp16-split projection GEMM (unchanged from R5) ----------------
#define APAD 40
template<int MODE>
__global__ __launch_bounds__(512) void tc_gemm(const float* __restrict__ bias,
                                               float* __restrict__ outp)
{
    __shared__ __half Ah[128][APAD], Al[128][APAD];
    __shared__ __half Bh[128][APAD], Bl[128][APAD];

    const int tid  = threadIdx.x;
    const int lane = tid & 31;
    const int wid  = tid >> 5;
    const int wm   = wid >> 2;
    const int wn   = wid & 3;
    const int m0 = blockIdx.y * 128;
    const int n0 = blockIdx.x * 128;

    const __half* pAh = (MODE == 0) ? g_xh  : g_aoh;
    const __half* pAl = (MODE == 0) ? g_xl  : g_aol;
    const __half* pBh = (MODE == 0) ? g_wqh : g_woh;
    const __half* pBl = (MODE == 0) ? g_wql : g_wol;

    const int grow = tid >> 2;
    const int gc   = (tid & 3) * 8;

    const __half* gAh = pAh + (size_t)(m0 + grow) * CC + gc;
    const __half* gAl = pAl + (size_t)(m0 + grow) * CC + gc;
    const __half* gBh = pBh + (size_t)(n0 + grow) * CC + gc;
    const __half* gBl = pBl + (size_t)(n0 + grow) * CC + gc;

    float acc[2][4][4];
#pragma unroll
    for (int i = 0; i < 2; i++)
#pragma unroll
        for (int j = 0; j < 4; j++)
#pragma unroll
            for (int c = 0; c < 4; c++) acc[i][j][c] = 0.0f;

    float4 rah = *(const float4*)gAh;
    float4 ral = *(const float4*)gAl;
    float4 rbh = *(const float4*)gBh;
    float4 rbl = *(const float4*)gBl;

    const uint32_t sAh = smem_u32(&Ah[0][0]);
    const uint32_t sAl = smem_u32(&Al[0][0]);
    const uint32_t sBh = smem_u32(&Bh[0][0]);
    const uint32_t sBl = smem_u32(&Bl[0][0]);

    const uint32_t a_row = wm * 32 + (lane & 15);
    const uint32_t a_kg  = (lane >> 4) << 3;
    const uint32_t b_kg  = ((lane >> 3) & 1) << 3;

    for (int k0 = 0; k0 < CC; k0 += 32) {
        __syncthreads();
        *(float4*)&Ah[grow][gc] = rah;
        *(float4*)&Al[grow][gc] = ral;
        *(float4*)&Bh[grow][gc] = rbh;
        *(float4*)&Bl[grow][gc] = rbl;
        __syncthreads();

        if (k0 + 32 < CC) {
            rah = *(const float4*)(gAh + k0 + 32);
            ral = *(const float4*)(gAl + k0 + 32);
            rbh = *(const float4*)(gBh + k0 + 32);
            rbl = *(const float4*)(gBl + k0 + 32);
        }

#pragma unroll
        for (int ks = 0; ks < 2; ks++) {
            const uint32_t kcol = ks * 16;
            uint32_t ah[2][4], al[2][4];
#pragma unroll
            for (int mt = 0; mt < 2; mt++) {
                uint32_t off = ((a_row + mt * 16) * APAD + kcol + a_kg) * 2;
                ldsm_x4(ah[mt], sAh + off);
                ldsm_x4(al[mt], sAl + off);
            }
#pragma unroll
            for (int nt = 0; nt < 4; nt++) {
                uint32_t boff = ((wn * 32 + nt * 8 + (lane & 7)) * APAD + kcol + b_kg) * 2;
                uint32_t bhr[2], blr[2];
                ldsm_x2(bhr, sBh + boff);
                ldsm_x2(blr, sBl + boff);
#pragma unroll
                for (int mt = 0; mt < 2; mt++) {
                    mma16816(acc[mt][nt], ah[mt], bhr);
                    mma16816(acc[mt][nt], ah[mt], blr);
                    mma16816(acc[mt][nt], al[mt], bhr);
                }
            }
        }
    }

#pragma unroll
    for (int mt = 0; mt < 2; mt++) {
#pragma unroll
        for (int nt = 0; nt < 4; nt++) {
            const float* c = acc[mt][nt];
            const int col = n0 + wn * 32 + nt * 8 + (lane & 3) * 2;
#pragma unroll
            for (int hr = 0; hr < 2; hr++) {
                const int row = m0 + wm * 32 + mt * 16 + (lane >> 2) + hr * 8;
                float2 val = make_float2(c[hr * 2 + 0], c[hr * 2 + 1]);
                if (MODE == 0) {
                    const int part = col >> 10, rr = col & 1023;
                    const int h = rr >> 6, d = rr & 63;
                    float* dst = (part == 0) ? g_q : (part == 1) ? g_k : g_v;
                    const int b = row >> 11, n = row & 2047;
                    *(float2*)&dst[((size_t)(b * HH + h) * NN + n) * DD + d] = val;
                } else {
                    val.x += bias[col];
                    val.y += bias[col + 1];
                    *(float2*)&outp[(size_t)row * CC + col] = val;
                }
            }
        }
    }
}

// ---------------- MMA flash attention ----------------
// Block = (bh, 128-query tile), 8 warps x 16 queries. fp16 hi/lo splits.
// Scores: QhKh + QhKl + QlKh. PV: PhVh + PhVl + PlVh.
#define KVS 72   // smem row stride in halves (144B: conflict-free ldmatrix)
__global__ __launch_bounds__(256) void attn_mma_kernel()
{
    const int bh   = blockIdx.y;
    const int q0   = blockIdx.x * 128;
    const int tid  = threadIdx.x;
    const int lane = tid & 31;
    const int warp = tid >> 5;

    const float* Qp = g_q + (size_t)bh * NN * DD;
    const float* Kp = g_k + (size_t)bh * NN * DD;
    const float* Vp = g_v + (size_t)bh * NN * DD;

    // 36864 B: Q phase = Qh[128][72], Ql[128][72]; KV phase = Kh/Kl/Vh/Vl [64][72]
    __shared__ __align__(16) __half sm[18432];
    __half* Qh = sm;          __half* Ql = sm + 9216;
    __half* Kh = sm;          __half* Kl = sm + 4608;
    __half* Vh = sm + 9216;   __half* Vl = sm + 13824;
    const uint32_t sQh = smem_u32(Qh), sQl = smem_u32(Ql);
    const uint32_t sKh = smem_u32(Kh), sKl = smem_u32(Kl);
    const uint32_t sVh = smem_u32(Vh), sVl = smem_u32(Vl);

    // ---- load Q tile (128x64 fp32), split into smem ----
#pragma unroll
    for (int i = 0; i < 8; i++) {
        int idx = tid + i * 256;                 // 2048 float4 slots
        int row = idx >> 4, c4 = (idx & 15) * 4;
        float4 v = *(const float4*)&Qp[(size_t)(q0 + row) * DD + c4];
        __half h0 = __float2half_rn(v.x), h1 = __float2half_rn(v.y);
        __half h2 = __float2half_rn(v.z), h3 = __float2half_rn(v.w);
        __half2 hl0 = __halves2half2(h0, h1), hl1 = __halves2half2(h2, h3);
        __half2 ll0 = __halves2half2(__float2half_rn(v.x - __half2float(h0)),
                                     __float2half_rn(v.y - __half2float(h1)));
        __half2 ll1 = __halves2half2(__float2half_rn(v.z - __half2float(h2)),
                                     __float2half_rn(v.w - __half2float(h3)));
        *(__half2*)&Qh[row * KVS + c4]     = hl0;
        *(__half2*)&Qh[row * KVS + c4 + 2] = hl1;
        *(__half2*)&Ql[row * KVS + c4]     = ll0;
        *(__half2*)&Ql[row * KVS + c4 + 2] = ll1;
    }
    __syncthreads();

    // ---- Q fragments: 4 k-steps x 4 regs (hi and lo) ----
    uint32_t qh[4][4], ql[4][4];
    {
        const uint32_t arow = warp * 16 + (lane & 15);
        const uint32_t akg  = ((lane >> 4) & 1) * 8;
#pragma unroll
        for (int ks = 0; ks < 4; ks++) {
            uint32_t off = (arow * KVS + ks * 16 + akg) * 2;
            ldsm_x4(qh[ks], sQh + off);
            ldsm_x4(ql[ks], sQl + off);
        }
    }
    __syncthreads();   // Q smem now reusable for K/V

    // ---- running state ----
    float O[8][4];
#pragma unroll
    for (int n = 0; n < 8; n++)
#pragma unroll
        for (int c = 0; c < 4; c++) O[n][c] = 0.0f;
    float m0r = -1e30f, m1r = -1e30f;
    float l0 = 0.0f, l1 = 0.0f;

    const uint32_t bkey = (lane & 7);
    const uint32_t bkg  = ((lane >> 3) & 1) * 8;
    const uint32_t vrow = (lane & 15);

    for (int j0 = 0; j0 < NN; j0 += 64) {
        // ---- load + split K,V tiles (64x64 each) ----
#pragma unroll
        for (int i = 0; i < 4; i++) {
            int idx = tid + i * 256;             // 1024 float4 slots
            int row = idx >> 4, c4 = (idx & 15) * 4;
            float4 kv = *(const float4*)&Kp[(size_t)(j0 + row) * DD + c4];
            float4 vv = *(const float4*)&Vp[(size_t)(j0 + row) * DD + c4];
            __half kh0 = __float2half_rn(kv.x), kh1 = __float2half_rn(kv.y);
            __half kh2 = __float2half_rn(kv.z), kh3 = __float2half_rn(kv.w);
            *(__half2*)&Kh[row * KVS + c4]     = __halves2half2(kh0, kh1);
            *(__half2*)&Kh[row * KVS + c4 + 2] = __halves2half2(kh2, kh3);
            *(__half2*)&Kl[row * KVS + c4]     = __halves2half2(
                __float2half_rn(kv.x - __half2float(kh0)), __float2half_rn(kv.y - __half2float(kh1)));
            *(__half2*)&Kl[row * KVS + c4 + 2] = __halves2half2(
                __float2half_rn(kv.z - __half2float(kh2)), __float2half_rn(kv.w - __half2float(kh3)));
            __half vh0 = __float2half_rn(vv.x), vh1 = __float2half_rn(vv.y);
            __half vh2 = __float2half_rn(vv.z), vh3 = __float2half_rn(vv.w);
            *(__half2*)&Vh[row * KVS + c4]     = __halves2half2(vh0, vh1);
            *(__half2*)&Vh[row * KVS + c4 + 2] = __halves2half2(vh2, vh3);
            *(__half2*)&Vl[row * KVS + c4]     = __halves2half2(
                __float2half_rn(vv.x - __half2float(vh0)), __float2half_rn(vv.y - __half2float(vh1)));
            *(__half2*)&Vl[row * KVS + c4 + 2] = __halves2half2(
                __float2half_rn(vv.z - __half2float(vh2)), __float2half_rn(vv.w - __half2float(vh3)));
        }
        __syncthreads();

        // ---- scores S = Q . K^T (3-term split), 16x64 per warp ----
        float s[8][4];
#pragma unroll
        for (int n = 0; n < 8; n++)
#pragma unroll
            for (int c = 0; c < 4; c++) s[n][c] = 0.0f;

#pragma unroll
        for (int ks = 0; ks < 4; ks++) {
#pragma unroll
            for (int nt = 0; nt < 8; nt++) {
                uint32_t boff = ((nt * 8 + bkey) * KVS + ks * 16 + bkg) * 2;
                uint32_t kbh[2], kbl[2];
                ldsm_x2(kbh, sKh + boff);
                ldsm_x2(kbl, sKl + boff);
                mma16816(s[nt], qh[ks], kbh);
                mma16816(s[nt], qh[ks], kbl);
                mma16816(s[nt], ql[ks], kbh);
            }
        }

        // ---- online softmax (rows r = lane>>2 and r+8) ----
        float mloc0 = -1e30f, mloc1 = -1e30f;
#pragma unroll
        for (int nt = 0; nt < 8; nt++) {
#pragma unroll
            for (int c = 0; c < 4; c++) s[nt][c] *= 0.125f;
            mloc0 = fmaxf(mloc0, fmaxf(s[nt][0], s[nt][1]));
            mloc1 = fmaxf(mloc1, fmaxf(s[nt][2], s[nt][3]));
        }
        mloc0 = fmaxf(mloc0, __shfl_xor_sync(0xffffffffu, mloc0, 1));
        mloc0 = fmaxf(mloc0, __shfl_xor_sync(0xffffffffu, mloc0, 2));
        mloc1 = fmaxf(mloc1, __shfl_xor_sync(0xffffffffu, mloc1, 1));
        mloc1 = fmaxf(mloc1, __shfl_xor_sync(0xffffffffu, mloc1, 2));

        float mn0 = fmaxf(m0r, mloc0), mn1 = fmaxf(m1r, mloc1);
        float cr0 = __expf(m0r - mn0), cr1 = __expf(m1r - mn1);
        m0r = mn0; m1r = mn1;
        l0 *= cr0; l1 *= cr1;
#pragma unroll
        for (int n = 0; n < 8; n++) {
            O[n][0] *= cr0; O[n][1] *= cr0;
            O[n][2] *= cr1; O[n][3] *= cr1;
        }

        float ls0 = 0.0f, ls1 = 0.0f;
        uint32_t aPh[4][4], aPl[4][4];
#pragma unroll
        for (int nt = 0; nt < 8; nt++) {
            float p0 = __expf(s[nt][0] - m0r);
            float p1 = __expf(s[nt][1] - m0r);
            float p2 = __expf(s[nt][2] - m1r);
            float p3 = __expf(s[nt][3] - m1r);
            ls0 += p0 + p1; ls1 += p2 + p3;
            __half h0 = __float2half_rn(p0), h1 = __float2half_rn(p1);
            __half h2 = __float2half_rn(p2), h3 = __float2half_rn(p3);
            const int kt = nt >> 1, hi2 = (nt & 1) * 2;
            aPh[kt][hi2 + 0] = packh2(h0, h1);
            aPh[kt][hi2 + 1] = packh2(h2, h3);
            aPl[kt][hi2 + 0] = packh2(__float2half_rn(p0 - __half2float(h0)),
                                      __float2half_rn(p1 - __half2float(h1)));
            aPl[kt][hi2 + 1] = packh2(__float2half_rn(p2 - __half2float(h2)),
                                      __float2half_rn(p3 - __half2float(h3)));
        }
        ls0 += __shfl_xor_sync(0xffffffffu, ls0, 1);
        ls0 += __shfl_xor_sync(0xffffffffu, ls0, 2);
        ls1 += __shfl_xor_sync(0xffffffffu, ls1, 1);
        ls1 += __shfl_xor_sync(0xffffffffu, ls1, 2);
        l0 += ls0; l1 += ls1;

        // NOTE: A-fragment order is {a0a1,a2a3,a4a5,a6a7} =
        // {c01 of nt=2kt, c23 of nt=2kt, c01 of nt=2kt+1, c23 of nt=2kt+1}  -> matches fill above.

        // ---- O += P . V (3-term split) ----
#pragma unroll
        for (int kt = 0; kt < 4; kt++) {
#pragma unroll
            for (int nd = 0; nd < 8; nd++) {
                uint32_t voff = ((kt * 16 + vrow) * KVS + nd * 8) * 2;
                uint32_t vbh[2], vbl[2];
                ldsm_x2t(vbh, sVh + voff);
                ldsm_x2t(vbl, sVl + voff);
                mma16816(O[nd], aPh[kt], vbh);
                mma16816(O[nd], aPh[kt], vbl);
                mma16816(O[nd], aPl[kt], vbh);
            }
        }
        __syncthreads();
    }

    // ---- epilogue ----
    const float inv0 = 1.0f / l0, inv1 = 1.0f / l1;
    const int b = bh >> 4, h = bh & 15;
    const int row0 = q0 + warp * 16 + (lane >> 2);
    const int row1 = row0 + 8;
#pragma unroll
    for (int nd = 0; nd < 8; nd++) {
        const int d = nd * 8 + (lane & 3) * 2;
        *(float2*)&g_ao[((size_t)(b * NN + row0)) * CC + h * DD + d] =
            make_float2(O[nd][0] * inv0, O[nd][1] * inv0);
        *(float2*)&g_ao[((size_t)(b * NN + row1)) * CC + h * DD + d] =
            make_float2(O[nd][2] * inv1, O[nd][3] * inv1);
    }
}

// ---------------------------------------------------------------------------
extern "C" void kernel_launch(void* const* d_in, const int* in_sizes, int n_in,
                              void* d_out, int out_size)
{
    const float* x     = (const float*)d_in[0];
    const float* W_qkv = (const float*)d_in[1];
    const float* W_out = (const float*)d_in[2];
    const float* b_out = (const float*)d_in[3];
    float* out = (float*)d_out;
    (void)in_sizes; (void)n_in; (void)out_size;

    split_kernel<<<(MM * CC / 4 + 255) / 256, 256>>>(x,     0, MM * CC / 4);
    split_kernel<<<(E3 * CC / 4 + 255) / 256, 256>>>(W_qkv, 1, E3 * CC / 4);
    split_kernel<<<(CC * CC / 4 + 255) / 256, 256>>>(W_out, 2, CC * CC / 4);

    {
        dim3 grid(E3 / 128, MM / 128);
        tc_gemm<0><<<grid, 512>>>(nullptr, nullptr);
    }
    {
        dim3 grid(NN / 128, BH);
        attn_mma_kernel<<<grid, 256>>>();
    }
    split_kernel<<<(MM * CC / 4 + 255) / 256, 256>>>(nullptr, 3, MM * CC / 4);
    {
        dim3 grid(CC / 128, MM / 128);
        tc_gemm<1><<<grid, 512>>>(b_out, out);
    }
}

// round 7
// speedup vs baseline: 3.3148x; 1.0635x over previous
#include <cuda_runtime.h>
#include <cuda_fp16.h>
#include <cstdint>
#include <math.h>

#define BB 2
#define NN 2048
#define CC 1024
#define HH 16
#define DD 64
#define E3 3072
#define MM (BB*NN)   // 4096
#define BH (BB*HH)   // 32

// ---------------- scratch (no allocations allowed) ----------------
__device__ float g_q [BH * NN * DD];
__device__ float g_k [BH * NN * DD];
__device__ float g_v [BH * NN * DD];
__device__ float g_ao[MM * CC];

__device__ __forceinline__ uint32_t smem_u32(const void* p) {
    uint32_t a;
    asm("{ .reg .u64 t; cvta.to.shared.u64 t, %1; cvt.u32.u64 %0, t; }" : "=r"(a) : "l"(p));
    return a;
}
__device__ __forceinline__ void mma16816(float* c, const uint32_t* a, const uint32_t* b) {
    asm volatile("mma.sync.aligned.m16n8k16.row.col.f32.f16.f16.f32 "
        "{%0,%1,%2,%3}, {%4,%5,%6,%7}, {%8,%9}, {%0,%1,%2,%3};"
        : "+f"(c[0]), "+f"(c[1]), "+f"(c[2]), "+f"(c[3])
        : "r"(a[0]), "r"(a[1]), "r"(a[2]), "r"(a[3]), "r"(b[0]), "r"(b[1]));
}
__device__ __forceinline__ void ldsm_x4(uint32_t* r, uint32_t addr) {
    asm volatile("ldmatrix.sync.aligned.m8n8.x4.shared.b16 {%0,%1,%2,%3}, [%4];"
        : "=r"(r[0]), "=r"(r[1]), "=r"(r[2]), "=r"(r[3]) : "r"(addr));
}
__device__ __forceinline__ void ldsm_x2(uint32_t* r, uint32_t addr) {
    asm volatile("ldmatrix.sync.aligned.m8n8.x2.shared.b16 {%0,%1}, [%2];"
        : "=r"(r[0]), "=r"(r[1]) : "r"(addr));
}
__device__ __forceinline__ void ldsm_x2t(uint32_t* r, uint32_t addr) {
    asm volatile("ldmatrix.sync.aligned.m8n8.x2.trans.shared.b16 {%0,%1}, [%2];"
        : "=r"(r[0]), "=r"(r[1]) : "r"(addr));
}
__device__ __forceinline__ uint32_t packh2(__half a, __half b) {
    __half2 t = __halves2half2(a, b);
    return *reinterpret_cast<uint32_t*>(&t);
}
// fp32x4 -> (hi half2x2, lo half2x2)
__device__ __forceinline__ void cvt_split(float4 v, uint2& h, uint2& l) {
    __half h0 = __float2half_rn(v.x), h1 = __float2half_rn(v.y);
    __half h2 = __float2half_rn(v.z), h3 = __float2half_rn(v.w);
    h.x = packh2(h0, h1); h.y = packh2(h2, h3);
    l.x = packh2(__float2half_rn(v.x - __half2float(h0)),
                 __float2half_rn(v.y - __half2float(h1)));
    l.y = packh2(__float2half_rn(v.z - __half2float(h2)),
                 __float2half_rn(v.w - __half2float(h3)));
}

// ---------------- mma.sync fp16-split GEMM, double-buffered, inline split --------
// D[m=token][n=feature] = sum_k A[m][k]*B[n][k], products AhBh+AhBl+AlBh.
// Tile 128x128, BK=32, 512 threads = 16 warps (4x4), warp tile 32x32.
// Dynamic smem: 2 stages x (Ah|Al|Bh|Bl)[128][40] halves = 81920 B.
// MODE 0: A = x, B = W_qkv, scatter to g_q/g_k/g_v.  MODE 1: A = g_ao, B = W_out, +bias.
#define GSMEM 81920
template<int MODE>
__global__ __launch_bounds__(512) void tc_gemm(const float* __restrict__ Ain,
                                               const float* __restrict__ Bin,
                                               const float* __restrict__ bias,
                                               float* __restrict__ outp)
{
    extern __shared__ __half sm[];
    const int tid  = threadIdx.x;
    const int lane = tid & 31;
    const int wid  = tid >> 5;
    const int wm   = wid >> 2;
    const int wn   = wid & 3;
    const int m0 = blockIdx.y * 128;  // token tile
    const int n0 = blockIdx.x * 128;  // feature tile

    const float* pA = (MODE == 0) ? Ain : g_ao;
    const float* pB = Bin;

    const uint32_t sbase = smem_u32(sm);
    const uint32_t a_row = wm * 32 + (lane & 15);
    const uint32_t a_kg  = (lane >> 4) << 3;
    const uint32_t b_kg  = ((lane >> 3) & 1) << 3;

    float acc[2][4][4];
#pragma unroll
    for (int i = 0; i < 2; i++)
#pragma unroll
        for (int j = 0; j < 4; j++)
#pragma unroll
            for (int c = 0; c < 4; c++) acc[i][j][c] = 0.0f;

    // global slots: 1024 float4 per matrix per 32-chunk; 2 per thread
    float4 ra[2], rb[2];
#pragma unroll
    for (int i = 0; i < 2; i++) {
        int slot = tid + i * 512;
        int row = slot >> 3, c4 = (slot & 7) * 4;
        ra[i] = *(const float4*)&pA[(size_t)(m0 + row) * CC + c4];
        rb[i] = *(const float4*)&pB[(size_t)(n0 + row) * CC + c4];
    }

    // store chunk into stage st (half-index offsets: Ah 0, Al 5120, Bh 10240, Bl 15360)
    auto store_chunk = [&](int st) {
#pragma unroll
        for (int i = 0; i < 2; i++) {
            int slot = tid + i * 512;
            int row = slot >> 3, c = (slot & 7) * 4;
            uint2 h, l;
            cvt_split(ra[i], h, l);
            *(uint2*)&sm[st * 20480 +         row * 40 + c] = h;
            *(uint2*)&sm[st * 20480 +  5120 + row * 40 + c] = l;
            cvt_split(rb[i], h, l);
            *(uint2*)&sm[st * 20480 + 10240 + row * 40 + c] = h;
            *(uint2*)&sm[st * 20480 + 15360 + row * 40 + c] = l;
        }
    };

    store_chunk(0);
    __syncthreads();

    for (int k0 = 0; k0 < CC; k0 += 32) {
        const int st = (k0 >> 5) & 1;
        if (k0 + 32 < CC) {
#pragma unroll
            for (int i = 0; i < 2; i++) {
                int slot = tid + i * 512;
                int row = slot >> 3, c4 = (slot & 7) * 4;
                ra[i] = *(const float4*)&pA[(size_t)(m0 + row) * CC + k0 + 32 + c4];
                rb[i] = *(const float4*)&pB[(size_t)(n0 + row) * CC + k0 + 32 + c4];
            }
        }

        const uint32_t base = sbase + st * 40960;   // bytes
#pragma unroll
        for (int ks = 0; ks < 2; ks++) {
            const uint32_t kcol = ks * 16;
            uint32_t ah[2][4], al[2][4];
#pragma unroll
            for (int mt = 0; mt < 2; mt++) {
                uint32_t off = ((a_row + mt * 16) * 40 + kcol + a_kg) * 2;
                ldsm_x4(ah[mt], base + off);
                ldsm_x4(al[mt], base + 10240 + off);
            }
#pragma unroll
            for (int nt = 0; nt < 4; nt++) {
                uint32_t boff = ((wn * 32 + nt * 8 + (lane & 7)) * 40 + kcol + b_kg) * 2;
                uint32_t bhr[2], blr[2];
                ldsm_x2(bhr, base + 20480 + boff);
                ldsm_x2(blr, base + 30720 + boff);
#pragma unroll
                for (int mt = 0; mt < 2; mt++) {
                    mma16816(acc[mt][nt], ah[mt], bhr);
                    mma16816(acc[mt][nt], ah[mt], blr);
                    mma16816(acc[mt][nt], al[mt], bhr);
                }
            }
        }

        if (k0 + 32 < CC) store_chunk(st ^ 1);
        __syncthreads();
    }

    // Epilogue
#pragma unroll
    for (int mt = 0; mt < 2; mt++) {
#pragma unroll
        for (int nt = 0; nt < 4; nt++) {
            const float* c = acc[mt][nt];
            const int col = n0 + wn * 32 + nt * 8 + (lane & 3) * 2;
#pragma unroll
            for (int hr = 0; hr < 2; hr++) {
                const int row = m0 + wm * 32 + mt * 16 + (lane >> 2) + hr * 8;
                float2 val = make_float2(c[hr * 2 + 0], c[hr * 2 + 1]);
                if (MODE == 0) {
                    const int part = col >> 10, rr = col & 1023;
                    const int h = rr >> 6, d = rr & 63;
                    float* dst = (part == 0) ? g_q : (part == 1) ? g_k : g_v;
                    const int b = row >> 11, n = row & 2047;
                    *(float2*)&dst[((size_t)(b * HH + h) * NN + n) * DD + d] = val;
                } else {
                    val.x += bias[col];
                    val.y += bias[col + 1];
                    *(float2*)&outp[(size_t)row * CC + col] = val;
                }
            }
        }
    }
}

// ---------------- MMA flash attention (unchanged from R6) ----------------
#define KVS 72
__global__ __launch_bounds__(256) void attn_mma_kernel()
{
    const int bh   = blockIdx.y;
    const int q0   = blockIdx.x * 128;
    const int tid  = threadIdx.x;
    const int lane = tid & 31;
    const int warp = tid >> 5;

    const float* Qp = g_q + (size_t)bh * NN * DD;
    const float* Kp = g_k + (size_t)bh * NN * DD;
    const float* Vp = g_v + (size_t)bh * NN * DD;

    __shared__ __align__(16) __half smh[18432];
    __half* Qh = smh;          __half* Ql = smh + 9216;
    __half* Kh = smh;          __half* Kl = smh + 4608;
    __half* Vh = smh + 9216;   __half* Vl = smh + 13824;
    const uint32_t sQh = smem_u32(Qh), sQl = smem_u32(Ql);
    const uint32_t sKh = smem_u32(Kh), sKl = smem_u32(Kl);
    const uint32_t sVh = smem_u32(Vh), sVl = smem_u32(Vl);

#pragma unroll
    for (int i = 0; i < 8; i++) {
        int idx = tid + i * 256;
        int row = idx >> 4, c4 = (idx & 15) * 4;
        float4 v = *(const float4*)&Qp[(size_t)(q0 + row) * DD + c4];
        uint2 h, l;
        cvt_split(v, h, l);
        *(uint2*)&Qh[row * KVS + c4] = h;
        *(uint2*)&Ql[row * KVS + c4] = l;
    }
    __syncthreads();

    uint32_t qh[4][4], ql[4][4];
    {
        const uint32_t arow = warp * 16 + (lane & 15);
        const uint32_t akg  = ((lane >> 4) & 1) * 8;
#pragma unroll
        for (int ks = 0; ks < 4; ks++) {
            uint32_t off = (arow * KVS + ks * 16 + akg) * 2;
            ldsm_x4(qh[ks], sQh + off);
            ldsm_x4(ql[ks], sQl + off);
        }
    }
    __syncthreads();

    float O[8][4];
#pragma unroll
    for (int n = 0; n < 8; n++)
#pragma unroll
        for (int c = 0; c < 4; c++) O[n][c] = 0.0f;
    float m0r = -1e30f, m1r = -1e30f;
    float l0 = 0.0f, l1 = 0.0f;

    const uint32_t bkey = (lane & 7);
    const uint32_t bkg  = ((lane >> 3) & 1) * 8;
    const uint32_t vrow = (lane & 15);

    for (int j0 = 0; j0 < NN; j0 += 64) {
#pragma unroll
        for (int i = 0; i < 4; i++) {
            int idx = tid + i * 256;
            int row = idx >> 4, c4 = (idx & 15) * 4;
            float4 kv = *(const float4*)&Kp[(size_t)(j0 + row) * DD + c4];
            float4 vv = *(const float4*)&Vp[(size_t)(j0 + row) * DD + c4];
            uint2 h, l;
            cvt_split(kv, h, l);
            *(uint2*)&Kh[row * KVS + c4] = h;
            *(uint2*)&Kl[row * KVS + c4] = l;
            cvt_split(vv, h, l);
            *(uint2*)&Vh[row * KVS + c4] = h;
            *(uint2*)&Vl[row * KVS + c4] = l;
        }
        __syncthreads();

        float s[8][4];
#pragma unroll
        for (int n = 0; n < 8; n++)
#pragma unroll
            for (int c = 0; c < 4; c++) s[n][c] = 0.0f;

#pragma unroll
        for (int ks = 0; ks < 4; ks++) {
#pragma unroll
            for (int nt = 0; nt < 8; nt++) {
                uint32_t boff = ((nt * 8 + bkey) * KVS + ks * 16 + bkg) * 2;
                uint32_t kbh[2], kbl[2];
                ldsm_x2(kbh, sKh + boff);
                ldsm_x2(kbl, sKl + boff);
                mma16816(s[nt], qh[ks], kbh);
                mma16816(s[nt], qh[ks], kbl);
                mma16816(s[nt], ql[ks], kbh);
            }
        }

        float mloc0 = -1e30f, mloc1 = -1e30f;
#pragma unroll
        for (int nt = 0; nt < 8; nt++) {
#pragma unroll
            for (int c = 0; c < 4; c++) s[nt][c] *= 0.125f;
            mloc0 = fmaxf(mloc0, fmaxf(s[nt][0], s[nt][1]));
            mloc1 = fmaxf(mloc1, fmaxf(s[nt][2], s[nt][3]));
        }
        mloc0 = fmaxf(mloc0, __shfl_xor_sync(0xffffffffu, mloc0, 1));
        mloc0 = fmaxf(mloc0, __shfl_xor_sync(0xffffffffu, mloc0, 2));
        mloc1 = fmaxf(mloc1, __shfl_xor_sync(0xffffffffu, mloc1, 1));
        mloc1 = fmaxf(mloc1, __shfl_xor_sync(0xffffffffu, mloc1, 2));

        float mn0 = fmaxf(m0r, mloc0), mn1 = fmaxf(m1r, mloc1);
        float cr0 = __expf(m0r - mn0), cr1 = __expf(m1r - mn1);
        m0r = mn0; m1r = mn1;
        l0 *= cr0; l1 *= cr1;
#pragma unroll
        for (int n = 0; n < 8; n++) {
            O[n][0] *= cr0; O[n][1] *= cr0;
            O[n][2] *= cr1; O[n][3] *= cr1;
        }

        float ls0 = 0.0f, ls1 = 0.0f;
        uint32_t aPh[4][4], aPl[4][4];
#pragma unroll
        for (int nt = 0; nt < 8; nt++) {
            float p0 = __expf(s[nt][0] - m0r);
            float p1 = __expf(s[nt][1] - m0r);
            float p2 = __expf(s[nt][2] - m1r);
            float p3 = __expf(s[nt][3] - m1r);
            ls0 += p0 + p1; ls1 += p2 + p3;
            __half h0 = __float2half_rn(p0), h1 = __float2half_rn(p1);
            __half h2 = __float2half_rn(p2), h3 = __float2half_rn(p3);
            const int kt = nt >> 1, hi2 = (nt & 1) * 2;
            aPh[kt][hi2 + 0] = packh2(h0, h1);
            aPh[kt][hi2 + 1] = packh2(h2, h3);
            aPl[kt][hi2 + 0] = packh2(__float2half_rn(p0 - __half2float(h0)),
                                      __float2half_rn(p1 - __half2float(h1)));
            aPl[kt][hi2 + 1] = packh2(__float2half_rn(p2 - __half2float(h2)),
                                      __float2half_rn(p3 - __half2float(h3)));
        }
        ls0 += __shfl_xor_sync(0xffffffffu, ls0, 1);
        ls0 += __shfl_xor_sync(0xffffffffu, ls0, 2);
        ls1 += __shfl_xor_sync(0xffffffffu, ls1, 1);
        ls1 += __shfl_xor_sync(0xffffffffu, ls1, 2);
        l0 += ls0; l1 += ls1;

#pragma unroll
        for (int kt = 0; kt < 4; kt++) {
#pragma unroll
            for (int nd = 0; nd < 8; nd++) {
                uint32_t voff = ((kt * 16 + vrow) * KVS + nd * 8) * 2;
                uint32_t vbh[2], vbl[2];
                ldsm_x2t(vbh, sVh + voff);
                ldsm_x2t(vbl, sVl + voff);
                mma16816(O[nd], aPh[kt], vbh);
                mma16816(O[nd], aPh[kt], vbl);
                mma16816(O[nd], aPl[kt], vbh);
            }
        }
        __syncthreads();
    }

    const float inv0 = 1.0f / l0, inv1 = 1.0f / l1;
    const int b = bh >> 4, h = bh & 15;
    const int row0 = q0 + warp * 16 + (lane >> 2);
    const int row1 = row0 + 8;
#pragma unroll
    for (int nd = 0; nd < 8; nd++) {
        const int d = nd * 8 + (lane & 3) * 2;
        *(float2*)&g_ao[((size_t)(b * NN + row0)) * CC + h * DD + d] =
            make_float2(O[nd][0] * inv0, O[nd][1] * inv0);
        *(float2*)&g_ao[((size_t)(b * NN + row1)) * CC + h * DD + d] =
            make_float2(O[nd][2] * inv1, O[nd][3] * inv1);
    }
}

// ---------------------------------------------------------------------------
extern "C" void kernel_launch(void* const* d_in, const int* in_sizes, int n_in,
                              void* d_out, int out_size)
{
    const float* x     = (const float*)d_in[0];
    const float* W_qkv = (const float*)d_in[1];
    const float* W_out = (const float*)d_in[2];
    const float* b_out = (const float*)d_in[3];
    float* out = (float*)d_out;
    (void)in_sizes; (void)n_in; (void)out_size;

    cudaFuncSetAttribute(tc_gemm<0>, cudaFuncAttributeMaxDynamicSharedMemorySize, GSMEM);
    cudaFuncSetAttribute(tc_gemm<1>, cudaFuncAttributeMaxDynamicSharedMemorySize, GSMEM);

    // 1) QKV projection (inline fp16 split), scatter to g_q/g_k/g_v
    {
        dim3 grid(E3 / 128, MM / 128);   // (24, 32)
        tc_gemm<0><<<grid, 512, GSMEM>>>(x, W_qkv, nullptr, nullptr);
    }
    // 2) Flash attention (mma.sync)
    {
        dim3 grid(NN / 128, BH);
        attn_mma_kernel<<<grid, 256>>>();
    }
    // 3) Output projection + bias
    {
        dim3 grid(CC / 128, MM / 128);   // (8, 32)
        tc_gemm<1><<<grid, 512, GSMEM>>>(nullptr, W_out, b_out, out);
    }
}